// round 4
// baseline (speedup 1.0000x reference)
#include <cuda_runtime.h>
#include <math.h>

#define NBATCH 1024
#define SGRID  28
#define CELLS  (NBATCH * SGRID * SGRID)   // 802816 = 3136 * 256 exactly
#define TPB    256
#define BLOCKS (CELLS / TPB)              // 3136
#define L_COORD 5.0
#define L_NOOBJ 0.5

// Global scratch: [cls, noobj_raw, contain, reg_raw(xy+wh)]
__device__ double g_acc[4];
__device__ int g_mask_mode;   // 0 = uint8, 1 = int32, 2 = float32

// ---------------------------------------------------------------------------
// Setup: zero accumulators + detect mask storage dtype from first 1KB.
//  - f32 bool: nonzero words are exactly 0x3F800000
//  - u8  bool: packed bytes -> some word has a nonzero high byte (w > 1)
//  - i32 bool: words are exactly 0 or 1
// ---------------------------------------------------------------------------
__global__ void yolo_setup_kernel(const unsigned int* __restrict__ mask_words) {
    if (threadIdx.x == 0 && blockIdx.x == 0) {
        g_acc[0] = 0.0; g_acc[1] = 0.0; g_acc[2] = 0.0; g_acc[3] = 0.0;
        int mode = 1;  // default: int32
        for (int i = 0; i < 256; i++) {
            unsigned int w = mask_words[i];
            if (w == 0x3F800000u) { mode = 2; break; }   // float32 1.0f
            if (w > 1u)           { mode = 0; break; }   // packed uint8 bytes
        }
        g_mask_mode = mode;
    }
}

__device__ __forceinline__ float iou_vs_target(
    float bx, float by, float bw, float bh,
    float tx1, float ty1, float tx2, float ty2, float t_area)
{
    const float inv_s = 1.0f / (float)SGRID;
    float bxc = bx * inv_s, byc = by * inv_s;
    float x1 = bxc - 0.5f * bw, y1 = byc - 0.5f * bh;
    float x2 = bxc + 0.5f * bw, y2 = byc + 0.5f * bh;
    float lx = fmaxf(x1, tx1), ly = fmaxf(y1, ty1);
    float rx = fminf(x2, tx2), ry = fminf(y2, ty2);
    float iw = fmaxf(rx - lx, 0.0f), ih = fmaxf(ry - ly, 0.0f);
    float inter = iw * ih;
    float b_area = (x2 - x1) * (y2 - y1);
    float den = b_area + t_area - inter;
    return inter / (den > 0.0f ? den : 1.0f);
}

__global__ void __launch_bounds__(TPB) yolo_main_kernel(
    const float* __restrict__ pred,
    const float* __restrict__ tbox,
    const float* __restrict__ tcls,
    const void*  __restrict__ maskp)
{
    __shared__ __align__(16) float s_pred[TPB * 30];   // 30720 B
    __shared__ float  s_maskf[TPB];                    // 1024 B (1.0 / 0.0)
    __shared__ float4 warp_sums[TPB / 32];             // 128 B
    // total static smem: 31872 B  (< 48 KB static limit)

    const int tid  = threadIdx.x;
    const int i    = blockIdx.x * TPB + tid;   // global cell; CELLS % TPB == 0
    const int mode = g_mask_mode;

    // ---- phase 0: mask into smem ----
    bool m;
    if (mode == 0)      m = __ldg(((const unsigned char*)maskp) + i) != 0;
    else if (mode == 1) m = __ldg(((const int*)maskp) + i) != 0;
    else                m = __ldg(((const float*)maskp) + i) != 0.0f;
    s_maskf[tid] = m ? 1.0f : 0.0f;
    __syncthreads();

    // ---- phase 1: mask-predicated pred staging (coalesced float4) ----
    {
        const float4* gp4 = (const float4*)(pred + (size_t)blockIdx.x * (TPB * 30));
        float4* sp4 = (float4*)s_pred;
#pragma unroll
        for (int k = 0; k < 8; k++) {               // 1920 float4s; 7.5/thread
            int idx = tid + k * TPB;
            if (idx < TPB * 30 / 4) {
                int e0 = 4 * idx;                   // first float covered
                int c0 = e0 / 30;
                int c1 = (e0 + 3) / 30;             // last float's cell (<= c0+1)
                if (s_maskf[c0] != 0.0f || s_maskf[c1] != 0.0f)
                    sp4[idx] = gp4[idx];
            }
        }
    }

    // unmasked cells: fetch only the two confidences, straight from gmem
    float no_c1 = 0.0f, no_c2 = 0.0f;
    if (!m) {
        const float* pg = pred + (size_t)i * 30;
        no_c1 = __ldg(pg + 4);
        no_c2 = __ldg(pg + 9);
    }
    // masked cells: fetch target box (predicated float4, coalesced)
    float4 tb = make_float4(0.f, 0.f, 0.f, 0.f);
    if (m) tb = __ldg((const float4*)tbox + i);

    __syncthreads();

    float a_cls = 0.0f, a_no = 0.0f, a_cont = 0.0f, a_reg = 0.0f;

    // ---- phase 2: box losses (per-thread, from smem) ----
    if (!m) {
        a_no = no_c1 * no_c1 + no_c2 * no_c2;
    } else {
        const float* p = s_pred + tid * 30;    // stride 30: conflict-free

        float tx = tb.x, ty = tb.y, tw = tb.z, th = tb.w;
        const float inv_s = 1.0f / (float)SGRID;
        float txc = tx * inv_s, tyc = ty * inv_s;
        float tx1 = txc - 0.5f * tw, ty1 = tyc - 0.5f * th;
        float tx2 = txc + 0.5f * tw, ty2 = tyc + 0.5f * th;
        float t_area = (tx2 - tx1) * (ty2 - ty1);

        float p0 = p[0], p1 = p[1], p2 = p[2], p3 = p[3], p4 = p[4];
        float p5 = p[5], p6 = p[6], p7 = p[7], p8 = p[8], p9 = p[9];

        float i1 = iou_vs_target(p0, p1, p2, p3, tx1, ty1, tx2, ty2, t_area);
        float i2 = iou_vs_target(p5, p6, p7, p8, tx1, ty1, tx2, ty2, t_area);

        bool take1 = i1 > i2;
        float best_iou = take1 ? i1 : i2;
        float bx = take1 ? p0 : p5;
        float by = take1 ? p1 : p6;
        float bw = take1 ? p2 : p7;
        float bh = take1 ? p3 : p8;
        float bc = take1 ? p4 : p9;

        float dx = bx - tx, dy = by - ty;
        a_reg = dx * dx + dy * dy;
        float sw = sqrtf(bw) - sqrtf(tw);
        float sh = sqrtf(bh) - sqrtf(th);
        a_reg += sw * sw + sh * sh;
        float dc = bc - best_iou;
        a_cont = dc * dc;
    }

    // ---- phase 3: cls loss, cooperative coalesced sweep of tcls ----
    // element e in [0, TPB*20): cell = e/20, class j = e%20
    {
        const float4* gc4 = (const float4*)(tcls + (size_t)blockIdx.x * (TPB * 20));
#pragma unroll
        for (int k = 0; k < 5; k++) {               // 1280 float4s; 5/thread
            int idx = tid + k * TPB;
            int e0 = 4 * idx;
            int c0 = e0 / 20;
            int c1 = (e0 + 3) / 20;
            float m0 = s_maskf[c0];
            float m1 = s_maskf[c1];
            if (m0 != 0.0f || m1 != 0.0f) {
                float4 t4 = __ldg(gc4 + idx);
                float tv[4] = {t4.x, t4.y, t4.z, t4.w};
#pragma unroll
                for (int c = 0; c < 4; c++) {
                    int e    = e0 + c;
                    int cell = e / 20;
                    int j    = e - cell * 20;
                    float fm = s_maskf[cell];
                    float d  = s_pred[cell * 30 + 10 + j] - tv[c];
                    a_cls = fmaf(fm * d, d, a_cls);
                }
            }
        }
    }

    // ---- reduce: warp shuffle -> block -> 4 double atomics ----
    const unsigned fullmask = 0xFFFFFFFFu;
#pragma unroll
    for (int off = 16; off > 0; off >>= 1) {
        a_cls  += __shfl_down_sync(fullmask, a_cls,  off);
        a_no   += __shfl_down_sync(fullmask, a_no,   off);
        a_cont += __shfl_down_sync(fullmask, a_cont, off);
        a_reg  += __shfl_down_sync(fullmask, a_reg,  off);
    }

    int lane = tid & 31;
    int wid  = tid >> 5;
    if (lane == 0) warp_sums[wid] = make_float4(a_cls, a_no, a_cont, a_reg);
    __syncthreads();

    if (wid == 0) {
        float4 v = (lane < (TPB / 32)) ? warp_sums[lane]
                                       : make_float4(0.f, 0.f, 0.f, 0.f);
#pragma unroll
        for (int off = 4; off > 0; off >>= 1) {
            v.x += __shfl_down_sync(fullmask, v.x, off);
            v.y += __shfl_down_sync(fullmask, v.y, off);
            v.z += __shfl_down_sync(fullmask, v.z, off);
            v.w += __shfl_down_sync(fullmask, v.w, off);
        }
        if (lane == 0) {
            atomicAdd(&g_acc[0], (double)v.x);
            atomicAdd(&g_acc[1], (double)v.y);
            atomicAdd(&g_acc[2], (double)v.z);
            atomicAdd(&g_acc[3], (double)v.w);
        }
    }
}

__global__ void yolo_finalize_kernel(float* __restrict__ out) {
    if (threadIdx.x == 0 && blockIdx.x == 0) {
        double cls  = g_acc[0];
        double no   = L_NOOBJ * g_acc[1];
        double cont = g_acc[2];
        double reg  = L_COORD * g_acc[3];
        double total = cls + no + cont + reg;
        const double invN = 1.0 / (double)NBATCH;
        out[0] = (float)(total * invN);
        out[1] = (float)(reg   * invN);
        out[2] = (float)(cont  * invN);
        out[3] = (float)(no    * invN);
        out[4] = (float)(cls   * invN);
    }
}

extern "C" void kernel_launch(void* const* d_in, const int* in_sizes, int n_in,
                              void* d_out, int out_size)
{
    const float* pred = (const float*)d_in[0];
    const float* tbox = (const float*)d_in[1];
    const float* tcls = (const float*)d_in[2];
    const void*  mask = d_in[3];

    yolo_setup_kernel<<<1, 32>>>((const unsigned int*)mask);
    yolo_main_kernel<<<BLOCKS, TPB>>>(pred, tbox, tcls, mask);
    yolo_finalize_kernel<<<1, 32>>>((float*)d_out);
}

// round 10
// speedup vs baseline: 1.3003x; 1.3003x over previous
#include <cuda_runtime.h>
#include <math.h>

#define NBATCH 1024
#define SGRID  28
#define CELLS  (NBATCH * SGRID * SGRID)   // 802816 = 3136 * 256 exactly
#define TPB    256
#define BLOCKS (CELLS / TPB)              // 3136
#define L_COORD 5.0
#define L_NOOBJ 0.5

// Per-block partial sums: x=cls, y=noobj_raw, z=contain, w=reg_raw
__device__ float4 g_part[BLOCKS];
__device__ unsigned int g_count;      // zero-initialized; reset by last block

__device__ __forceinline__ float iou_vs_target(
    float bx, float by, float bw, float bh,
    float tx1, float ty1, float tx2, float ty2, float t_area)
{
    const float inv_s = 1.0f / (float)SGRID;
    float bxc = bx * inv_s, byc = by * inv_s;
    float x1 = bxc - 0.5f * bw, y1 = byc - 0.5f * bh;
    float x2 = bxc + 0.5f * bw, y2 = byc + 0.5f * bh;
    float lx = fmaxf(x1, tx1), ly = fmaxf(y1, ty1);
    float rx = fminf(x2, tx2), ry = fminf(y2, ty2);
    float iw = fmaxf(rx - lx, 0.0f), ih = fmaxf(ry - ly, 0.0f);
    float inter = iw * ih;
    float b_area = (x2 - x1) * (y2 - y1);
    float den = b_area + t_area - inter;
    return inter / (den > 0.0f ? den : 1.0f);
}

__global__ void __launch_bounds__(TPB) yolo_main_kernel(
    const float* __restrict__ pred,
    const float* __restrict__ tbox,
    const float* __restrict__ tcls,
    const void*  __restrict__ maskp,
    float* __restrict__ out)
{
    __shared__ __align__(16) float s_pred[TPB * 30];   // 30720 B
    __shared__ float  s_maskf[TPB];                    // 1024 B
    __shared__ float4 warp_sums[TPB / 32];             // 128 B
    __shared__ int    s_is_last;                       // written by w0l0, read post-barrier
    __shared__ int    s_f32, s_u8;

    const int tid = threadIdx.x;
    const int i   = blockIdx.x * TPB + tid;   // CELLS % TPB == 0, no guard

    // ---- phase -1: inline mask dtype detection (first 1KB of mask buffer) ----
    //  - f32 bool: nonzero words are exactly 0x3F800000
    //  - u8  bool: packed {0,1} bytes -> some word > 1 (a byte above byte0 set)
    //  - i32 bool: words are exactly 0 or 1
    if (tid == 0) { s_f32 = 0; s_u8 = 0; }
    __syncthreads();
    {
        unsigned int w = __ldg((const unsigned int*)maskp + tid);  // L2 broadcast
        if (w == 0x3F800000u) s_f32 = 1;     // benign race: only writes of 1
        else if (w > 1u)      s_u8  = 1;
    }
    __syncthreads();
    const int mode = s_f32 ? 2 : (s_u8 ? 0 : 1);

    // ---- phase 0: mask into smem ----
    bool m;
    if (mode == 0)      m = __ldg(((const unsigned char*)maskp) + i) != 0;
    else if (mode == 1) m = __ldg(((const int*)maskp) + i) != 0;
    else                m = __ldg(((const float*)maskp) + i) != 0.0f;
    s_maskf[tid] = m ? 1.0f : 0.0f;
    __syncthreads();

    // ---- phase 1: mask-predicated pred staging (coalesced float4) ----
    {
        const float4* gp4 = (const float4*)(pred + (size_t)blockIdx.x * (TPB * 30));
        float4* sp4 = (float4*)s_pred;
#pragma unroll
        for (int k = 0; k < 8; k++) {               // 1920 float4s
            int idx = tid + k * TPB;
            if (idx < TPB * 30 / 4) {
                int e0 = 4 * idx;
                int c0 = e0 / 30;
                int c1 = (e0 + 3) / 30;
                if (s_maskf[c0] != 0.0f || s_maskf[c1] != 0.0f)
                    sp4[idx] = __ldg(gp4 + idx);
            }
        }
    }

    // unmasked cells: only the two confidences, direct from gmem
    float no_c1 = 0.0f, no_c2 = 0.0f;
    if (!m) {
        const float* pg = pred + (size_t)i * 30;
        no_c1 = __ldg(pg + 4);
        no_c2 = __ldg(pg + 9);
    }
    // masked cells: target box (predicated, coalesced float4)
    float4 tb = make_float4(0.f, 0.f, 0.f, 0.f);
    if (m) tb = __ldg((const float4*)tbox + i);

    __syncthreads();

    float a_cls = 0.0f, a_no = 0.0f, a_cont = 0.0f, a_reg = 0.0f;

    // ---- phase 2: box losses ----
    if (!m) {
        a_no = no_c1 * no_c1 + no_c2 * no_c2;
    } else {
        const float* p = s_pred + tid * 30;    // stride 30: conflict-free

        float tx = tb.x, ty = tb.y, tw = tb.z, th = tb.w;
        const float inv_s = 1.0f / (float)SGRID;
        float txc = tx * inv_s, tyc = ty * inv_s;
        float tx1 = txc - 0.5f * tw, ty1 = tyc - 0.5f * th;
        float tx2 = txc + 0.5f * tw, ty2 = tyc + 0.5f * th;
        float t_area = (tx2 - tx1) * (ty2 - ty1);

        float p0 = p[0], p1 = p[1], p2 = p[2], p3 = p[3], p4 = p[4];
        float p5 = p[5], p6 = p[6], p7 = p[7], p8 = p[8], p9 = p[9];

        float i1 = iou_vs_target(p0, p1, p2, p3, tx1, ty1, tx2, ty2, t_area);
        float i2 = iou_vs_target(p5, p6, p7, p8, tx1, ty1, tx2, ty2, t_area);

        bool take1 = i1 > i2;
        float best_iou = take1 ? i1 : i2;
        float bx = take1 ? p0 : p5;
        float by = take1 ? p1 : p6;
        float bw = take1 ? p2 : p7;
        float bh = take1 ? p3 : p8;
        float bc = take1 ? p4 : p9;

        float dx = bx - tx, dy = by - ty;
        a_reg = dx * dx + dy * dy;
        float sw = sqrtf(bw) - sqrtf(tw);
        float sh = sqrtf(bh) - sqrtf(th);
        a_reg += sw * sw + sh * sh;
        float dc = bc - best_iou;
        a_cont = dc * dc;
    }

    // ---- phase 3: cls loss, cooperative sweep ----
    // 20 floats/cell = exactly 5 float4s -> a float4 never spans cells.
    {
        const float4* gc4 = (const float4*)(tcls + (size_t)blockIdx.x * (TPB * 20));
#pragma unroll
        for (int k = 0; k < 5; k++) {               // 1280 float4s
            int idx  = tid + k * TPB;
            int cell = idx / 5;
            int q    = idx - cell * 5;
            if (s_maskf[cell] != 0.0f) {
                float4 t4 = __ldg(gc4 + idx);
                const float* pp = s_pred + cell * 30 + 10 + 4 * q;
                float d0 = pp[0] - t4.x;
                float d1 = pp[1] - t4.y;
                float d2 = pp[2] - t4.z;
                float d3 = pp[3] - t4.w;
                a_cls = fmaf(d0, d0, a_cls);
                a_cls = fmaf(d1, d1, a_cls);
                a_cls = fmaf(d2, d2, a_cls);
                a_cls = fmaf(d3, d3, a_cls);
            }
        }
    }

    // ---- block reduce: warp shuffle -> smem -> warp0 ----
    const unsigned fullmask = 0xFFFFFFFFu;
#pragma unroll
    for (int off = 16; off > 0; off >>= 1) {
        a_cls  += __shfl_down_sync(fullmask, a_cls,  off);
        a_no   += __shfl_down_sync(fullmask, a_no,   off);
        a_cont += __shfl_down_sync(fullmask, a_cont, off);
        a_reg  += __shfl_down_sync(fullmask, a_reg,  off);
    }

    int lane = tid & 31;
    int wid  = tid >> 5;
    if (lane == 0) warp_sums[wid] = make_float4(a_cls, a_no, a_cont, a_reg);
    __syncthreads();

    if (wid == 0) {
        float4 v = (lane < (TPB / 32)) ? warp_sums[lane]
                                       : make_float4(0.f, 0.f, 0.f, 0.f);
#pragma unroll
        for (int off = 4; off > 0; off >>= 1) {
            v.x += __shfl_down_sync(fullmask, v.x, off);
            v.y += __shfl_down_sync(fullmask, v.y, off);
            v.z += __shfl_down_sync(fullmask, v.z, off);
            v.w += __shfl_down_sync(fullmask, v.w, off);
        }
        if (lane == 0) {
            g_part[blockIdx.x] = v;          // no atomic contention
            __threadfence();
            unsigned int ticket = atomicAdd(&g_count, 1u);
            s_is_last = (ticket == BLOCKS - 1) ? 1 : 0;
        }
    }
    __syncthreads();

    // ---- last block: deterministic final reduction + output + reset ----
    if (s_is_last) {
        __threadfence();                     // acquire: see all g_part writes
        double r_cls = 0.0, r_no = 0.0, r_cont = 0.0, r_reg = 0.0;
        for (int b = tid; b < BLOCKS; b += TPB) {   // fixed per-thread order
            float4 v = g_part[b];
            r_cls  += (double)v.x;
            r_no   += (double)v.y;
            r_cont += (double)v.z;
            r_reg  += (double)v.w;
        }
#pragma unroll
        for (int off = 16; off > 0; off >>= 1) {
            r_cls  += __shfl_down_sync(fullmask, r_cls,  off);
            r_no   += __shfl_down_sync(fullmask, r_no,   off);
            r_cont += __shfl_down_sync(fullmask, r_cont, off);
            r_reg  += __shfl_down_sync(fullmask, r_reg,  off);
        }
        __shared__ double s_d[4][TPB / 32];
        if (lane == 0) {
            s_d[0][wid] = r_cls; s_d[1][wid] = r_no;
            s_d[2][wid] = r_cont; s_d[3][wid] = r_reg;
        }
        __syncthreads();
        if (tid == 0) {
            double cls = 0.0, no = 0.0, cont = 0.0, reg = 0.0;
#pragma unroll
            for (int wsum = 0; wsum < TPB / 32; wsum++) {
                cls  += s_d[0][wsum]; no   += s_d[1][wsum];
                cont += s_d[2][wsum]; reg  += s_d[3][wsum];
            }
            no  *= L_NOOBJ;
            reg *= L_COORD;
            double total = cls + no + cont + reg;
            const double invN = 1.0 / (double)NBATCH;
            out[0] = (float)(total * invN);
            out[1] = (float)(reg   * invN);
            out[2] = (float)(cont  * invN);
            out[3] = (float)(no    * invN);
            out[4] = (float)(cls   * invN);
            g_count = 0;                     // reset for next graph replay
        }
    }
}

extern "C" void kernel_launch(void* const* d_in, const int* in_sizes, int n_in,
                              void* d_out, int out_size)
{
    const float* pred = (const float*)d_in[0];
    const float* tbox = (const float*)d_in[1];
    const float* tcls = (const float*)d_in[2];
    const void*  mask = d_in[3];

    yolo_main_kernel<<<BLOCKS, TPB>>>(pred, tbox, tcls, mask, (float*)d_out);
}

// round 14
// speedup vs baseline: 1.5854x; 1.2193x over previous
#include <cuda_runtime.h>
#include <math.h>

#define NBATCH 1024
#define SGRID  28
#define CELLS  (NBATCH * SGRID * SGRID)   // 802816 = 3136 * 256 exactly
#define TPB    256
#define WPB    (TPB / 32)                 // 8 warps
#define BLOCKS (CELLS / TPB)              // 3136
#define L_COORD 5.0
#define L_NOOBJ 0.5

// Per-block partial sums: x=cls, y=noobj_raw, z=contain, w=reg_raw
__device__ float4 g_part[BLOCKS];
__device__ unsigned int g_count;      // zero-initialized; reset by last block

__device__ __forceinline__ float iou_vs_target(
    float bx, float by, float bw, float bh,
    float tx1, float ty1, float tx2, float ty2, float t_area)
{
    const float inv_s = 1.0f / (float)SGRID;
    float bxc = bx * inv_s, byc = by * inv_s;
    float x1 = bxc - 0.5f * bw, y1 = byc - 0.5f * bh;
    float x2 = bxc + 0.5f * bw, y2 = byc + 0.5f * bh;
    float lx = fmaxf(x1, tx1), ly = fmaxf(y1, ty1);
    float rx = fminf(x2, tx2), ry = fminf(y2, ty2);
    float iw = fmaxf(rx - lx, 0.0f), ih = fmaxf(ry - ly, 0.0f);
    float inter = iw * ih;
    float b_area = (x2 - x1) * (y2 - y1);
    float den = b_area + t_area - inter;
    return inter / (den > 0.0f ? den : 1.0f);
}

__global__ void __launch_bounds__(TPB) yolo_main_kernel(
    const float* __restrict__ pred,
    const float* __restrict__ tbox,
    const float* __restrict__ tcls,
    const void*  __restrict__ maskp,
    float* __restrict__ out)
{
    __shared__ __align__(16) float s_pred[TPB * 30];   // 30720 B
    __shared__ float  s_mf[TPB];                       // 1024 B (1.0 / 0.0)
    __shared__ int    s_vote[WPB];                     // u8-dtype warp votes
    __shared__ float4 warp_sums[WPB];
    __shared__ int    s_is_last;

    const int tid = threadIdx.x;
    const int i   = blockIdx.x * TPB + tid;   // CELLS % TPB == 0, no guard

    // ================= front-batched independent loads =================
    // (a) dtype detect word from first 1KB of mask (safe for all dtypes).
    //     u8 iff some word > 1 and != 0x3F800000 (packed {0,1} bytes).
    unsigned int wdet = __ldg((const unsigned int*)maskp + tid);
    bool u8vote = (wdet > 1u) && (wdet != 0x3F800000u);
    s_vote[tid >> 5] = __any_sync(0xFFFFFFFFu, u8vote) ? 1 : 0;

    // (b) target box, unconditional coalesced float4
    float4 tb = __ldg((const float4*)tbox + i);

    // (c) unconditional pred staging: 1920 float4s, perfectly coalesced,
    //     all independent -> maximal MLP, front-batched by ptxas.
    {
        const float4* gp4 = (const float4*)(pred + (size_t)blockIdx.x * (TPB * 30));
        float4* sp4 = (float4*)s_pred;
#pragma unroll
        for (int k = 0; k < 8; k++) {
            int idx = tid + k * TPB;
            if (idx < TPB * 30 / 4) sp4[idx] = __ldg(gp4 + idx);
        }
    }

    __syncthreads();   // s_vote + s_pred visible

    // ---- mask load (mode-predicated: word read OOB-unsafe if u8) ----
    // i32 bool and f32 bool are both "word != 0" -> one shared path.
    int u8mode = 0;
#pragma unroll
    for (int wv = 0; wv < WPB; wv++) u8mode |= s_vote[wv];

    bool m;
    if (u8mode) m = __ldg((const unsigned char*)maskp + i) != 0;
    else        m = __ldg((const unsigned int*)maskp + i) != 0u;
    s_mf[tid] = m ? 1.0f : 0.0f;
    __syncthreads();   // s_mf visible

    // ================= compute =================
    float a_cls = 0.0f, a_no = 0.0f, a_cont = 0.0f, a_reg = 0.0f;

    // ---- box losses ----
    {
        const float* p = s_pred + tid * 30;    // stride 30: conflict-free
        float p4v = p[4], p9v = p[9];
        if (!m) {
            a_no = p4v * p4v + p9v * p9v;
        } else {
            float tx = tb.x, ty = tb.y, tw = tb.z, th = tb.w;
            const float inv_s = 1.0f / (float)SGRID;
            float txc = tx * inv_s, tyc = ty * inv_s;
            float tx1 = txc - 0.5f * tw, ty1 = tyc - 0.5f * th;
            float tx2 = txc + 0.5f * tw, ty2 = tyc + 0.5f * th;
            float t_area = (tx2 - tx1) * (ty2 - ty1);

            float p0 = p[0], p1 = p[1], p2 = p[2], p3 = p[3];
            float p5 = p[5], p6 = p[6], p7 = p[7], p8 = p[8];

            float i1 = iou_vs_target(p0, p1, p2, p3, tx1, ty1, tx2, ty2, t_area);
            float i2 = iou_vs_target(p5, p6, p7, p8, tx1, ty1, tx2, ty2, t_area);

            bool take1 = i1 > i2;
            float best_iou = take1 ? i1 : i2;
            float bx = take1 ? p0 : p5;
            float by = take1 ? p1 : p6;
            float bw = take1 ? p2 : p7;
            float bh = take1 ? p3 : p8;
            float bc = take1 ? p4v : p9v;

            float dx = bx - tx, dy = by - ty;
            a_reg = dx * dx + dy * dy;
            float sw = sqrtf(bw) - sqrtf(tw);
            float sh = sqrtf(bh) - sqrtf(th);
            a_reg += sw * sw + sh * sh;
            float dc = bc - best_iou;
            a_cont = dc * dc;
        }
    }

    // ---- cls loss: unconditional cooperative sweep (fm-weighted) ----
    // 20 floats/cell = exactly 5 float4s -> a float4 never spans cells.
    {
        const float4* gc4 = (const float4*)(tcls + (size_t)blockIdx.x * (TPB * 20));
#pragma unroll
        for (int k = 0; k < 5; k++) {               // 5 independent LDGs, batched
            int idx  = tid + k * TPB;
            int cell = idx / 5;
            int q    = idx - cell * 5;
            float4 t4 = __ldg(gc4 + idx);
            float fm  = s_mf[cell];
            const float* pp = s_pred + cell * 30 + 10 + 4 * q;
            float d0 = pp[0] - t4.x;
            float d1 = pp[1] - t4.y;
            float d2 = pp[2] - t4.z;
            float d3 = pp[3] - t4.w;
            float ssum = d0 * d0 + d1 * d1 + d2 * d2 + d3 * d3;
            a_cls = fmaf(fm, ssum, a_cls);
        }
    }

    // ---- block reduce: warp shuffle -> smem -> warp0 ----
    const unsigned fullmask = 0xFFFFFFFFu;
#pragma unroll
    for (int off = 16; off > 0; off >>= 1) {
        a_cls  += __shfl_down_sync(fullmask, a_cls,  off);
        a_no   += __shfl_down_sync(fullmask, a_no,   off);
        a_cont += __shfl_down_sync(fullmask, a_cont, off);
        a_reg  += __shfl_down_sync(fullmask, a_reg,  off);
    }

    int lane = tid & 31;
    int wid  = tid >> 5;
    if (lane == 0) warp_sums[wid] = make_float4(a_cls, a_no, a_cont, a_reg);
    __syncthreads();

    if (wid == 0) {
        float4 v = (lane < WPB) ? warp_sums[lane]
                                : make_float4(0.f, 0.f, 0.f, 0.f);
#pragma unroll
        for (int off = 4; off > 0; off >>= 1) {
            v.x += __shfl_down_sync(fullmask, v.x, off);
            v.y += __shfl_down_sync(fullmask, v.y, off);
            v.z += __shfl_down_sync(fullmask, v.z, off);
            v.w += __shfl_down_sync(fullmask, v.w, off);
        }
        if (lane == 0) {
            g_part[blockIdx.x] = v;          // no atomic contention
            __threadfence();
            unsigned int ticket = atomicAdd(&g_count, 1u);
            s_is_last = (ticket == BLOCKS - 1) ? 1 : 0;
        }
    }
    __syncthreads();

    // ---- last block: deterministic final reduction + output + reset ----
    if (s_is_last) {
        __threadfence();                     // acquire: see all g_part writes
        double r_cls = 0.0, r_no = 0.0, r_cont = 0.0, r_reg = 0.0;
        for (int b = tid; b < BLOCKS; b += TPB) {   // fixed per-thread order
            float4 v = g_part[b];
            r_cls  += (double)v.x;
            r_no   += (double)v.y;
            r_cont += (double)v.z;
            r_reg  += (double)v.w;
        }
#pragma unroll
        for (int off = 16; off > 0; off >>= 1) {
            r_cls  += __shfl_down_sync(fullmask, r_cls,  off);
            r_no   += __shfl_down_sync(fullmask, r_no,   off);
            r_cont += __shfl_down_sync(fullmask, r_cont, off);
            r_reg  += __shfl_down_sync(fullmask, r_reg,  off);
        }
        __shared__ double s_d[4][WPB];
        if (lane == 0) {
            s_d[0][wid] = r_cls; s_d[1][wid] = r_no;
            s_d[2][wid] = r_cont; s_d[3][wid] = r_reg;
        }
        __syncthreads();
        if (tid == 0) {
            double cls = 0.0, no = 0.0, cont = 0.0, reg = 0.0;
#pragma unroll
            for (int wsum = 0; wsum < WPB; wsum++) {
                cls  += s_d[0][wsum]; no   += s_d[1][wsum];
                cont += s_d[2][wsum]; reg  += s_d[3][wsum];
            }
            no  *= L_NOOBJ;
            reg *= L_COORD;
            double total = cls + no + cont + reg;
            const double invN = 1.0 / (double)NBATCH;
            out[0] = (float)(total * invN);
            out[1] = (float)(reg   * invN);
            out[2] = (float)(cont  * invN);
            out[3] = (float)(no    * invN);
            out[4] = (float)(cls   * invN);
            g_count = 0;                     // reset for next graph replay
        }
    }
}

extern "C" void kernel_launch(void* const* d_in, const int* in_sizes, int n_in,
                              void* d_out, int out_size)
{
    const float* pred = (const float*)d_in[0];
    const float* tbox = (const float*)d_in[1];
    const float* tcls = (const float*)d_in[2];
    const void*  mask = d_in[3];

    yolo_main_kernel<<<BLOCKS, TPB>>>(pred, tbox, tcls, mask, (float*)d_out);
}